// round 5
// baseline (speedup 1.0000x reference)
#include <cuda_runtime.h>
#include <math.h>
#include <stdint.h>

#define HIDDEN 4096
#define NEXP   128
#define TOPK   8
#define TM     128
#define KCH    32
#define NCHUNK (HIDDEN / KCH)

#define PITCH   36                    // bytes per 8-float row (9 float slots)
#define K8S     (128 * PITCH + 32)    // 4640 B per k8 region (+32B bank skew)
#define AREG    (4 * K8S)             // A region per stage
#define STAGE_B (2 * AREG)            // A + B per stage
#define LPITCH  132                   // logits smem pitch (floats)
#define SMEM_BYTES (2 * STAGE_B)

#define DELTA   1.5e-4f               // near-tie threshold on selection scores
#define RB      8                     // refine batch (tokens per CTA pass)

__device__ int g_ctr;
__device__ int g_list[16384];

// round-to-nearest tf32 split: h exactly representable in tf32, l = x-h exact
__device__ __forceinline__ void split_tf32(float x, uint32_t& h, uint32_t& l) {
    uint32_t hb = (__float_as_uint(x) + 0x1000u) & 0xFFFFE000u;
    h = hb;
    l = __float_as_uint(x - __uint_as_float(hb));
}

__device__ __forceinline__ void mma8(float d[4], const uint32_t a[4], const uint32_t b[2]) {
    asm volatile(
        "mma.sync.aligned.m16n8k8.row.col.f32.tf32.tf32.f32 "
        "{%0,%1,%2,%3}, {%4,%5,%6,%7}, {%8,%9}, {%0,%1,%2,%3};\n"
        : "+f"(d[0]), "+f"(d[1]), "+f"(d[2]), "+f"(d[3])
        : "r"(a[0]), "r"(a[1]), "r"(a[2]), "r"(a[3]),
          "r"(b[0]), "r"(b[1]));
}

__global__ void zero_ctr_kernel() { g_ctr = 0; }

// ---------------------------------------------------------------------------
// Kernel A: tf32x3 mma.sync GEMM (logits = X @ W^T) -> smem logits ->
// sigmoid -> top-9 with min-gap risk detection -> write provisional top-8.
// Risky tokens (near ties) get appended to g_list for exact fp32 refine.
// ---------------------------------------------------------------------------
__global__ void __launch_bounds__(256, 1) router_fused(
    const float* __restrict__ X, const float* __restrict__ W,
    const float* __restrict__ bias, float* __restrict__ out, int T)
{
    extern __shared__ char smem[];
    const int tid  = threadIdx.x;
    const int wid  = tid >> 5;
    const int lane = tid & 31;
    const int m0   = blockIdx.x * TM;
    const int wm   = wid >> 2;            // 0..1
    const int wn   = wid & 3;             // 0..3
    const int g    = lane >> 2;           // groupID
    const int t    = lane & 3;            // threadID_in_group

    const int c4   = tid & 7;
    const int k8p  = c4 >> 1;
    const int kkb  = (c4 & 1) * 4;

    float acc[4][4][4];
#pragma unroll
    for (int i = 0; i < 4; i++)
#pragma unroll
        for (int j = 0; j < 4; j++)
#pragma unroll
            for (int q = 0; q < 4; q++) acc[i][j][q] = 0.f;

    float4 xa[4], wa[4];

#pragma unroll
    for (int i = 0; i < 4; i++) {
        const int row = (tid >> 3) + 32 * i;
        xa[i] = *(const float4*)(X + (size_t)(m0 + row) * HIDDEN + c4 * 4);
        wa[i] = *(const float4*)(W + (size_t)row * HIDDEN + c4 * 4);
    }
#pragma unroll
    for (int i = 0; i < 4; i++) {
        const int row = (tid >> 3) + 32 * i;
        float* pA = (float*)(smem + k8p * K8S + row * PITCH + kkb * 4);
        pA[0] = xa[i].x; pA[1] = xa[i].y; pA[2] = xa[i].z; pA[3] = xa[i].w;
        float* pB = (float*)(smem + AREG + k8p * K8S + row * PITCH + kkb * 4);
        pB[0] = wa[i].x; pB[1] = wa[i].y; pB[2] = wa[i].z; pB[3] = wa[i].w;
    }

    for (int c = 0; c < NCHUNK; c++) {
        __syncthreads();
        const char* sp = smem + (c & 1) * STAGE_B;

        if (c + 1 < NCHUNK) {
            const int k0 = (c + 1) * KCH;
#pragma unroll
            for (int i = 0; i < 4; i++) {
                const int row = (tid >> 3) + 32 * i;
                xa[i] = *(const float4*)(X + (size_t)(m0 + row) * HIDDEN + k0 + c4 * 4);
                wa[i] = *(const float4*)(W + (size_t)row * HIDDEN + k0 + c4 * 4);
            }
        }

#pragma unroll
        for (int k8 = 0; k8 < 4; k8++) {
            const char* sB = sp + AREG + k8 * K8S + wn * (32 * PITCH);
            uint32_t bh[4][2], bl[4][2];
#pragma unroll
            for (int j = 0; j < 4; j++) {
                float b0 = *(const float*)(sB + (j * 8 + g) * PITCH + t * 4);
                float b1 = *(const float*)(sB + (j * 8 + g) * PITCH + (t + 4) * 4);
                split_tf32(b0, bh[j][0], bl[j][0]);
                split_tf32(b1, bh[j][1], bl[j][1]);
            }
            const char* sA = sp + k8 * K8S + wm * (64 * PITCH);
#pragma unroll
            for (int i = 0; i < 4; i++) {
                float a0 = *(const float*)(sA + (i * 16 + g)     * PITCH + t * 4);
                float a1 = *(const float*)(sA + (i * 16 + g + 8) * PITCH + t * 4);
                float a2 = *(const float*)(sA + (i * 16 + g)     * PITCH + (t + 4) * 4);
                float a3 = *(const float*)(sA + (i * 16 + g + 8) * PITCH + (t + 4) * 4);
                uint32_t ah[4], al[4];
                split_tf32(a0, ah[0], al[0]);
                split_tf32(a1, ah[1], al[1]);
                split_tf32(a2, ah[2], al[2]);
                split_tf32(a3, ah[3], al[3]);
#pragma unroll
                for (int j = 0; j < 4; j++) {
                    mma8(acc[i][j], ah, bh[j]);
                    mma8(acc[i][j], al, bh[j]);
                    mma8(acc[i][j], ah, bl[j]);
                }
            }
        }

        if (c + 1 < NCHUNK) {
            char* sn = smem + ((c + 1) & 1) * STAGE_B;
#pragma unroll
            for (int i = 0; i < 4; i++) {
                const int row = (tid >> 3) + 32 * i;
                float* pA = (float*)(sn + k8p * K8S + row * PITCH + kkb * 4);
                pA[0] = xa[i].x; pA[1] = xa[i].y; pA[2] = xa[i].z; pA[3] = xa[i].w;
                float* pB = (float*)(sn + AREG + k8p * K8S + row * PITCH + kkb * 4);
                pB[0] = wa[i].x; pB[1] = wa[i].y; pB[2] = wa[i].z; pB[3] = wa[i].w;
            }
        }
    }

    // ---- accumulators -> smem logits ----
    __syncthreads();
    float* L = (float*)smem;   // [128][LPITCH]
#pragma unroll
    for (int i = 0; i < 4; i++) {
        const int r0 = wm * 64 + i * 16 + g;
#pragma unroll
        for (int j = 0; j < 4; j++) {
            const int c0 = wn * 32 + j * 8 + t * 2;
            *(float2*)&L[r0 * LPITCH + c0]       = make_float2(acc[i][j][0], acc[i][j][1]);
            *(float2*)&L[(r0 + 8) * LPITCH + c0] = make_float2(acc[i][j][2], acc[i][j][3]);
        }
    }
    __syncthreads();

    // ---- top-9 with risk detection; warp w handles rows w*16..w*16+15 ----
    float bv[4];
#pragma unroll
    for (int q = 0; q < 4; q++) bv[q] = bias[q * 32 + lane];

    for (int rr = 0; rr < 16; rr++) {
        const int row = wid * 16 + rr;
        const float* Lr = L + row * LPITCH;

        float sv[4], wv[4];
#pragma unroll
        for (int q = 0; q < 4; q++) {
            float sc = 1.f / (1.f + expf(-Lr[q * 32 + lane]));
            wv[q] = sc;
            sv[q] = sc + bv[q];
        }

        float wsel[TOPK];
        int   isel[TOPK];
        float wsum = 0.f;
        float prev = 0.f, mingap = INFINITY;

#pragma unroll
        for (int k = 0; k < TOPK + 1; k++) {
            float bs = -INFINITY; int bi = 0x7fffffff; float bw = 0.f;
#pragma unroll
            for (int q = 0; q < 4; q++) {
                int e = q * 32 + lane;
                if (sv[q] > bs || (sv[q] == bs && e < bi)) { bs = sv[q]; bi = e; bw = wv[q]; }
            }
#pragma unroll
            for (int off = 16; off; off >>= 1) {
                float os = __shfl_xor_sync(0xffffffffu, bs, off);
                int   oi = __shfl_xor_sync(0xffffffffu, bi, off);
                float ow = __shfl_xor_sync(0xffffffffu, bw, off);
                if (os > bs || (os == bs && oi < bi)) { bs = os; bi = oi; bw = ow; }
            }
            if (k > 0) mingap = fminf(mingap, prev - bs);
            prev = bs;
            if (k < TOPK) {
                isel[k] = bi; wsel[k] = bw; wsum += bw;
#pragma unroll
                for (int q = 0; q < 4; q++)
                    if (q * 32 + lane == bi) sv[q] = -INFINITY;
            }
        }

        if (lane == 0) {
            const int token = m0 + row;
            float inv = 1.f / (wsum + 1e-20f);   // ROUTED_SCALING = 1.0
#pragma unroll
            for (int k = 0; k < TOPK; k++) {
                out[(size_t)token * TOPK + k]                    = (float)isel[k];
                out[(size_t)T * TOPK + (size_t)token * TOPK + k] = wsel[k] * inv;
            }
            if (!(mingap >= DELTA)) {                 // near tie (or NaN) -> refine
                int idx = atomicAdd(&g_ctr, 1);
                g_list[idx] = token;
            }
        }
    }
}

// ---------------------------------------------------------------------------
// Kernel C: exact fp32 refine of risky tokens. Batches of RB=8 tokens per CTA.
// thread (e = tid&127, tg = tid>>7): expert e, tokens tg*4..tg*4+3.
// X staged in smem in 512-float chunks; W rows streamed from L2.
// ---------------------------------------------------------------------------
__global__ void __launch_bounds__(256) refine_kernel(
    const float* __restrict__ X, const float* __restrict__ W,
    const float* __restrict__ bias, float* __restrict__ out, int T)
{
    __shared__ float Xs[RB][512];
    __shared__ float S[RB][NEXP];
    __shared__ int   tks[RB];

    const int tid  = threadIdx.x;
    const int e    = tid & 127;
    const int tg   = tid >> 7;
    const int wid  = tid >> 5;
    const int lane = tid & 31;
    const int R    = g_ctr;

    for (int b = blockIdx.x; b * RB < R; b += gridDim.x) {
        if (tid < RB) {
            int i = b * RB + tid;
            tks[tid] = (i < R) ? g_list[i] : -1;
        }
        __syncthreads();

        float acc[4] = {0.f, 0.f, 0.f, 0.f};
        const float* wrow = W + (size_t)e * HIDDEN;

        for (int c = 0; c < 8; c++) {
            const int k0 = c * 512;
#pragma unroll
            for (int i = 0; i < 4; i++) {
                int s   = tid + 256 * i;      // float4 slot 0..1023
                int tok = s >> 7;
                int f4  = s & 127;
                int tt  = tks[tok] < 0 ? 0 : tks[tok];
                *(float4*)&Xs[tok][f4 * 4] =
                    *(const float4*)(X + (size_t)tt * HIDDEN + k0 + f4 * 4);
            }
            __syncthreads();
#pragma unroll 4
            for (int f4 = 0; f4 < 128; f4++) {
                float4 w4 = *(const float4*)(wrow + k0 + f4 * 4);
#pragma unroll
                for (int j = 0; j < 4; j++) {
                    const float* xr = &Xs[tg * 4 + j][f4 * 4];
                    acc[j] = fmaf(w4.x, xr[0],
                             fmaf(w4.y, xr[1],
                             fmaf(w4.z, xr[2],
                             fmaf(w4.w, xr[3], acc[j]))));
                }
            }
            __syncthreads();
        }
#pragma unroll
        for (int j = 0; j < 4; j++) S[tg * 4 + j][e] = acc[j];
        __syncthreads();

        if (wid < RB && tks[wid] >= 0) {
            const int token = tks[wid];
            float sv[4], wv[4];
#pragma unroll
            for (int q = 0; q < 4; q++) {
                int ee = q * 32 + lane;
                float sc = 1.f / (1.f + expf(-S[wid][ee]));
                wv[q] = sc;
                sv[q] = sc + bias[ee];
            }
            float wsel[TOPK]; int isel[TOPK]; float wsum = 0.f;
#pragma unroll
            for (int k = 0; k < TOPK; k++) {
                float bs = -INFINITY; int bi = 0x7fffffff; float bw = 0.f;
#pragma unroll
                for (int q = 0; q < 4; q++) {
                    int ee = q * 32 + lane;
                    if (sv[q] > bs || (sv[q] == bs && ee < bi)) { bs = sv[q]; bi = ee; bw = wv[q]; }
                }
#pragma unroll
                for (int off = 16; off; off >>= 1) {
                    float os = __shfl_xor_sync(0xffffffffu, bs, off);
                    int   oi = __shfl_xor_sync(0xffffffffu, bi, off);
                    float ow = __shfl_xor_sync(0xffffffffu, bw, off);
                    if (os > bs || (os == bs && oi < bi)) { bs = os; bi = oi; bw = ow; }
                }
                isel[k] = bi; wsel[k] = bw; wsum += bw;
#pragma unroll
                for (int q = 0; q < 4; q++)
                    if (q * 32 + lane == bi) sv[q] = -INFINITY;
            }
            if (lane == 0) {
                float inv = 1.f / (wsum + 1e-20f);
#pragma unroll
                for (int k = 0; k < TOPK; k++) {
                    out[(size_t)token * TOPK + k]                    = (float)isel[k];
                    out[(size_t)T * TOPK + (size_t)token * TOPK + k] = wsel[k] * inv;
                }
            }
        }
        __syncthreads();
    }
}

// ---------------------------------------------------------------------------
extern "C" void kernel_launch(void* const* d_in, const int* in_sizes, int n_in,
                              void* d_out, int out_size)
{
    const float* X    = (const float*)d_in[0];   // hidden_states [T, 4096]
    const float* W    = (const float*)d_in[1];   // weight [128, 4096]
    const float* bias = (const float*)d_in[2];   // e_score_correction_bias [128]
    float* out = (float*)d_out;

    const int T = in_sizes[0] / HIDDEN;          // 16384

    cudaFuncSetAttribute(router_fused,
                         cudaFuncAttributeMaxDynamicSharedMemorySize, SMEM_BYTES);

    zero_ctr_kernel<<<1, 1>>>();
    router_fused<<<T / TM, 256, SMEM_BYTES>>>(X, W, bias, out, T);
    refine_kernel<<<256, 256>>>(X, W, bias, out, T);
}

// round 6
// speedup vs baseline: 1.3778x; 1.3778x over previous
#include <cuda_runtime.h>
#include <math.h>
#include <stdint.h>

#define HIDDEN 4096
#define NEXP   128
#define TOPK   8
#define TM     128
#define TK     8
#define NCHUNK (HIDDEN / TK)          // 512

#define XS_ROW 256                    // floats per k-row of duplicated A
#define WS_ROW 192                    // floats per k-row of B (16 blocks * 12)
#define XS_B   (TK * XS_ROW * 4)      // 8192 B
#define WS_B   (TK * WS_ROW * 4)      // 6144 B
#define STAGE_B (XS_B + WS_B)         // 14336 B
#define LPITCH 132
#define SMEM_BYTES (TM * LPITCH * 4)  // 67584 (stages 2*14336 fit inside)

// packed fp32 FMA: d.lo += a.lo*b.lo ; d.hi += a.hi*b.hi
__device__ __forceinline__ void ffma2(unsigned long long& d,
                                      unsigned long long a,
                                      unsigned long long b) {
    asm("fma.rn.f32x2 %0, %1, %2, %0;" : "+l"(d) : "l"(a), "l"(b));
}

// ---------------------------------------------------------------------------
// Fused router: packed-fp32 (f32x2) SGEMM  logits = X @ W^T  -> smem logits
// -> sigmoid -> top-8 (score = sigmoid + bias, lowest-index tie-break)
// -> normalize -> out = [indices_as_float | weights].
// One CTA per 128 tokens, 256 threads. Thread (tx=tid&15, ty=tid>>4) owns an
// 8(token) x 8(expert) micro-tile held as 8x4 packed expert-pairs.
// Numerics are bit-identical to the round-1 scalar fp32 kernel.
// ---------------------------------------------------------------------------
__global__ void __launch_bounds__(256, 1) router_fused(
    const float* __restrict__ X, const float* __restrict__ W,
    const float* __restrict__ bias, float* __restrict__ out, int T)
{
    extern __shared__ char smem[];
    const int tid  = threadIdx.x;
    const int wid  = tid >> 5;
    const int lane = tid & 31;
    const int tx   = tid & 15;         // expert block (8 experts)
    const int ty   = tid >> 4;         // token block  (8 tokens)
    const int m0   = blockIdx.x * TM;

    const int lr   = tid >> 1;         // load row 0..127
    const int lc   = (tid & 1) * 4;    // k offset 0 or 4

    unsigned long long acc[8][4];
#pragma unroll
    for (int i = 0; i < 8; i++)
#pragma unroll
        for (int j = 0; j < 4; j++) acc[i][j] = 0ull;

    const float* xptr = X + (size_t)(m0 + lr) * HIDDEN + lc;
    const float* wptr = W + (size_t)lr * HIDDEN + lc;

    // W smem slot for this loader thread (block pitch 12 floats = 48 B)
    const int wslot = ((lr >> 3) * 12 + (lr & 7)) * 4;

    float4 xa, wa;

    // ---- prologue: chunk 0 -> stage 0 ----
    xa = *(const float4*)(xptr);
    wa = *(const float4*)(wptr);
    {
        char* sp = smem;
        const float xv[4] = {xa.x, xa.y, xa.z, xa.w};
        const float wv[4] = {wa.x, wa.y, wa.z, wa.w};
#pragma unroll
        for (int j = 0; j < 4; j++) {
            *(float2*)(sp + (lc + j) * (XS_ROW * 4) + lr * 8) = make_float2(xv[j], xv[j]);
            *(float*)(sp + XS_B + (lc + j) * (WS_ROW * 4) + wslot) = wv[j];
        }
    }

    // ---- main loop: compute chunk c from stage c&1, prefetch+store c+1 ----
    for (int c = 0; c < NCHUNK; c++) {
        __syncthreads();
        const char* sp = smem + (c & 1) * STAGE_B;

        if (c + 1 < NCHUNK) {
            xa = *(const float4*)(xptr + (c + 1) * TK);
            wa = *(const float4*)(wptr + (c + 1) * TK);
        }

#pragma unroll
        for (int kk = 0; kk < TK; kk++) {
            const char* xrow = sp + kk * (XS_ROW * 4) + ty * 64;
            const char* wrow = sp + XS_B + kk * (WS_ROW * 4) + tx * 48;

            ulonglong2 a01 = *(const ulonglong2*)(xrow);
            ulonglong2 a23 = *(const ulonglong2*)(xrow + 16);
            ulonglong2 a45 = *(const ulonglong2*)(xrow + 32);
            ulonglong2 a67 = *(const ulonglong2*)(xrow + 48);
            ulonglong2 b01 = *(const ulonglong2*)(wrow);
            ulonglong2 b23 = *(const ulonglong2*)(wrow + 16);

            unsigned long long ar[8] = {a01.x, a01.y, a23.x, a23.y,
                                        a45.x, a45.y, a67.x, a67.y};
            unsigned long long br[4] = {b01.x, b01.y, b23.x, b23.y};
#pragma unroll
            for (int i = 0; i < 8; i++)
#pragma unroll
                for (int j = 0; j < 4; j++)
                    ffma2(acc[i][j], ar[i], br[j]);
        }

        if (c + 1 < NCHUNK) {
            char* sn = smem + ((c + 1) & 1) * STAGE_B;
            const float xv[4] = {xa.x, xa.y, xa.z, xa.w};
            const float wv[4] = {wa.x, wa.y, wa.z, wa.w};
#pragma unroll
            for (int j = 0; j < 4; j++) {
                *(float2*)(sn + (lc + j) * (XS_ROW * 4) + lr * 8) = make_float2(xv[j], xv[j]);
                *(float*)(sn + XS_B + (lc + j) * (WS_ROW * 4) + wslot) = wv[j];
            }
        }
    }

    // ---- epilogue: unpack accumulators -> smem logits ----
    __syncthreads();
    float* L = (float*)smem;   // [128][LPITCH]
#pragma unroll
    for (int i = 0; i < 8; i++) {
        const int r = ty * 8 + i;
#pragma unroll
        for (int j = 0; j < 4; j++) {
            float2 v = *(float2*)&acc[i][j];         // (expert e, e+1)
            *(float2*)&L[r * LPITCH + tx * 8 + j * 2] = v;
        }
    }
    __syncthreads();

    // ---- fused top-k: warp w handles rows w*16 .. w*16+15 ----
    float bv[4];
#pragma unroll
    for (int q = 0; q < 4; q++) bv[q] = bias[q * 32 + lane];

    for (int rr = 0; rr < 16; rr++) {
        const int row = wid * 16 + rr;
        const float* Lr = L + row * LPITCH;

        float sv[4], wv[4];
#pragma unroll
        for (int q = 0; q < 4; q++) {
            float sc = 1.f / (1.f + expf(-Lr[q * 32 + lane]));
            wv[q] = sc;
            sv[q] = sc + bv[q];
        }

        float wsel[TOPK];
        int   isel[TOPK];
        float wsum = 0.f;
#pragma unroll
        for (int k = 0; k < TOPK; k++) {
            float bs = -INFINITY; int bi = 0x7fffffff; float bw = 0.f;
#pragma unroll
            for (int q = 0; q < 4; q++) {
                int e = q * 32 + lane;
                if (sv[q] > bs || (sv[q] == bs && e < bi)) { bs = sv[q]; bi = e; bw = wv[q]; }
            }
#pragma unroll
            for (int off = 16; off; off >>= 1) {
                float os = __shfl_xor_sync(0xffffffffu, bs, off);
                int   oi = __shfl_xor_sync(0xffffffffu, bi, off);
                float ow = __shfl_xor_sync(0xffffffffu, bw, off);
                if (os > bs || (os == bs && oi < bi)) { bs = os; bi = oi; bw = ow; }
            }
            isel[k] = bi; wsel[k] = bw; wsum += bw;
#pragma unroll
            for (int q = 0; q < 4; q++)
                if (q * 32 + lane == bi) sv[q] = -INFINITY;
        }

        if (lane == 0) {
            const int token = m0 + row;
            float inv = 1.f / (wsum + 1e-20f);   // ROUTED_SCALING = 1.0
#pragma unroll
            for (int k = 0; k < TOPK; k++) {
                out[(size_t)token * TOPK + k]                    = (float)isel[k];
                out[(size_t)T * TOPK + (size_t)token * TOPK + k] = wsel[k] * inv;
            }
        }
    }
}

// ---------------------------------------------------------------------------
extern "C" void kernel_launch(void* const* d_in, const int* in_sizes, int n_in,
                              void* d_out, int out_size)
{
    const float* X    = (const float*)d_in[0];   // hidden_states [T, 4096]
    const float* W    = (const float*)d_in[1];   // weight [128, 4096]
    const float* bias = (const float*)d_in[2];   // e_score_correction_bias [128]
    float* out = (float*)d_out;

    const int T = in_sizes[0] / HIDDEN;          // 16384

    cudaFuncSetAttribute(router_fused,
                         cudaFuncAttributeMaxDynamicSharedMemorySize, SMEM_BYTES);
    router_fused<<<T / TM, 256, SMEM_BYTES>>>(X, W, bias, out, T);
}